// round 6
// baseline (speedup 1.0000x reference)
#include <cuda_runtime.h>
#include <math.h>
#include <stdint.h>

#define NB 4
#define NP 8
#define NN 512
#define DM 128
#define NH 4
#define DK 32
#define NT 3
#define NROWS (NB*NP*NN)     // 16384
#define MAXNNZ 128
#define LISTDIM 136
#define LDP 132              // smem row stride (floats) for GEMM tiles

// Scratch (device globals)
__device__ float g_qkv[9][NROWS][DM];    // [t*3 + {Q,K,V}][row][d]
__device__ float g_attn[NT][NROWS][DM];  // per-t attention output
__device__ int   g_cnt[NT][NN];
__device__ int   g_rank[NT][NN];
__device__ int   g_rowOfRank[NT][NN];
__device__ int   g_nnzR[NT][NN];
__device__ int   g_colsT[NT][LISTDIM][NN];   // [t][i][rank] -> coalesced over rank
__device__ float g_valsT[NT][LISTDIM][NN];

__constant__ int c_which[NT] = {0, 1, 3};

// ---------------------------------------------------------------------------
__device__ __forceinline__ uint32_t smem_u32(const void* p) {
    uint32_t a;
    asm("{ .reg .u64 t; cvta.to.shared.u64 t, %1; cvt.u32.u64 %0, t; }" : "=r"(a) : "l"(p));
    return a;
}
__device__ __forceinline__ void cp16(uint32_t dst, const void* src) {
    asm volatile("cp.async.ca.shared.global [%0], [%1], 16;" :: "r"(dst), "l"(src));
}
#define CP_COMMIT() asm volatile("cp.async.commit_group;" ::: "memory")
#define CP_WAIT0()  asm volatile("cp.async.wait_group 0;" ::: "memory")

// m16n8k8 tf32 MMA, D += A*B (row x col). Raw fp32 bits are valid tf32
// operands (HW ignores the low 13 mantissa bits -> truncation rounding).
__device__ __forceinline__ void mma8(float d[4], const uint32_t a[4], const uint32_t b[2]) {
    asm volatile("mma.sync.aligned.m16n8k8.row.col.f32.tf32.tf32.f32 "
        "{%0,%1,%2,%3}, {%4,%5,%6,%7}, {%8,%9}, {%0,%1,%2,%3};"
        : "+f"(d[0]), "+f"(d[1]), "+f"(d[2]), "+f"(d[3])
        : "r"(a[0]), "r"(a[1]), "r"(a[2]), "r"(a[3]), "r"(b[0]), "r"(b[1]));
}

// ===========================================================================
// Kernel 1a: count nonzeros per selected-tm row
// ===========================================================================
__global__ void count_kernel(const float* __restrict__ tmall) {
    int wg   = (blockIdx.x * blockDim.x + threadIdx.x) >> 5;
    int lane = threadIdx.x & 31;
    if (wg >= NT * NN) return;
    int t = wg / NN, n = wg % NN;
    const float* row = tmall + ((size_t)c_which[t] * NN + n) * NN;
    int cnt = 0;
    for (int base = 0; base < NN; base += 32)
        cnt += __popc(__ballot_sync(0xffffffffu, row[base + lane] != 0.0f));
    if (lane == 0) g_cnt[t][n] = cnt < MAXNNZ ? cnt : MAXNNZ;
}

// ===========================================================================
// Kernel 1b: rank rows by cnt (stable, deterministic). Block per t.
// ===========================================================================
__global__ void rank_kernel() {
    __shared__ int sc[NN];
    int t = blockIdx.x, n = threadIdx.x;
    sc[n] = g_cnt[t][n];
    __syncthreads();
    int c = sc[n], r = 0;
    for (int m = 0; m < NN; m++) {
        int cm = sc[m];
        r += (cm < c) || (cm == c && m < n);
    }
    g_rank[t][n] = r;
    g_rowOfRank[t][r] = n;
    g_nnzR[t][r] = c;
}

// ===========================================================================
// Kernel 1c: fill transposed CSR at rank column (+1 zero pad)
// ===========================================================================
__global__ void fill_kernel(const float* __restrict__ tmall) {
    int wg   = (blockIdx.x * blockDim.x + threadIdx.x) >> 5;
    int lane = threadIdx.x & 31;
    if (wg >= NT * NN) return;
    int t = wg / NN, n = wg % NN;
    int rk = g_rank[t][n];
    const float* row = tmall + ((size_t)c_which[t] * NN + n) * NN;
    int cnt = 0;
    for (int base = 0; base < NN; base += 32) {
        float v = row[base + lane];
        unsigned b = __ballot_sync(0xffffffffu, v != 0.0f);
        if (v != 0.0f) {
            int pos = cnt + __popc(b & ((1u << lane) - 1u));
            if (pos < MAXNNZ) { g_colsT[t][pos][rk] = base + lane; g_valsT[t][pos][rk] = v; }
        }
        cnt += __popc(b);
    }
    if (lane == 0) {
        int cc = cnt < MAXNNZ ? cnt : MAXNNZ;
        g_colsT[t][cc][rk] = 0;
        g_valsT[t][cc][rk] = 0.0f;
    }
}

// ===========================================================================
// Kernel 2: QKV projections via tf32 mma.sync. 128-row tiles, 512 threads /
// 16 warps (4x4 grid of 32x32 tiles); 9 weight slots; W double-buffered,
// staged with cp.async so the prefetch overlaps MMA.
// ===========================================================================
__global__ void __launch_bounds__(512, 1)
qkv_mma_kernel(const float* __restrict__ X,
               const float* __restrict__ Wq,
               const float* __restrict__ Wk,
               const float* __restrict__ Wv) {
    extern __shared__ uint32_t sm[];
    uint32_t* Xs = sm;                          // [128][LDP]
    uint32_t* Wsb0 = sm + 128 * LDP;
    uint32_t* Wsb1 = sm + 2 * 128 * LDP;
    int tid = threadIdx.x, lane = tid & 31, wid = tid >> 5;
    int mw = wid & 3, nw = wid >> 2;
    int g = lane >> 2, q = lane & 3;
    int row0 = blockIdx.x * 128;

    uint32_t xs_u  = smem_u32(Xs);
    uint32_t w0_u  = smem_u32(Wsb0);
    uint32_t w1_u  = smem_u32(Wsb1);

    const float* Wbase[3] = {Wq, Wk, Wv};
    for (int i = tid; i < 128 * 32; i += 512) {
        int r = i >> 5, k = (i & 31) << 2;
        cp16(xs_u + (r * LDP + k) * 4, X + (size_t)(row0 + r) * DM + k);
        cp16(w0_u + (r * LDP + k) * 4, Wbase[0] + (size_t)r * DM + k);
    }
    CP_COMMIT(); CP_WAIT0();
    __syncthreads();

    const uint32_t* abase = Xs + (mw * 32 + g) * LDP + q;

    for (int slot = 0; slot < 9; slot++) {
        if (slot < 8) {
            int ns = slot + 1;
            const float* W = Wbase[ns % 3] + (size_t)(ns / 3) * DM * DM;
            uint32_t dst = (ns & 1) ? w1_u : w0_u;
            for (int i = tid; i < 128 * 32; i += 512) {
                int r = i >> 5, k = (i & 31) << 2;
                cp16(dst + (r * LDP + k) * 4, W + (size_t)r * DM + k);
            }
            CP_COMMIT();
        }
        const uint32_t* bbase = ((slot & 1) ? Wsb1 : Wsb0) + (nw * 32 + g) * LDP + q;

        float acc[2][4][4];
        #pragma unroll
        for (int t2 = 0; t2 < 2; t2++)
            #pragma unroll
            for (int j = 0; j < 4; j++)
                #pragma unroll
                for (int e = 0; e < 4; e++) acc[t2][j][e] = 0.f;

        #pragma unroll 4
        for (int ks = 0; ks < 16; ks++) {
            int k0 = ks * 8;
            uint32_t a[2][4];
            #pragma unroll
            for (int t2 = 0; t2 < 2; t2++) {
                const uint32_t* ap = abase + t2 * 16 * LDP + k0;
                a[t2][0] = ap[0]; a[t2][1] = ap[8 * LDP];
                a[t2][2] = ap[4]; a[t2][3] = ap[8 * LDP + 4];
            }
            #pragma unroll
            for (int j = 0; j < 4; j++) {
                const uint32_t* bp = bbase + j * 8 * LDP + k0;
                uint32_t b[2]; b[0] = bp[0]; b[1] = bp[4];
                mma8(acc[0][j], a[0], b);
                mma8(acc[1][j], a[1], b);
            }
        }
        float* out = &g_qkv[slot][row0][0];
        #pragma unroll
        for (int t2 = 0; t2 < 2; t2++) {
            int r = mw * 32 + t2 * 16 + g;
            #pragma unroll
            for (int j = 0; j < 4; j++) {
                int c = nw * 32 + j * 8 + q * 2;
                *(float2*)(out + (size_t)r * DM + c)       = make_float2(acc[t2][j][0], acc[t2][j][1]);
                *(float2*)(out + (size_t)(r + 8) * DM + c) = make_float2(acc[t2][j][2], acc[t2][j][3]);
            }
        }
        CP_WAIT0();
        __syncthreads();
    }
}

// ===========================================================================
// Kernel 3: sparse-masked attention. Block = (t,bp,h), 512 threads, thread =
// rank (rows sorted by nnz -> uniform warp iteration counts). K/V in SMEM
// stride-32, lane-rotated float4 reads (4-phase crossbar floor). Direct exp;
// pairwise (2-entry) inner loop for ILP on the LDS->dot->exp->accum chain.
// ===========================================================================
__global__ void __launch_bounds__(512, 1)
attn_kernel() {
    extern __shared__ float smf[];
    float* Ks = smf;               // [512][32]
    float* Vs = smf + 512 * 32;    // [512][32]
    int tid = threadIdx.x;
    int h = blockIdx.x;
    int t = blockIdx.y >> 5, bp = blockIdx.y & 31;

    const float* Kg = &g_qkv[t * 3 + 1][(size_t)bp * NN][0];
    const float* Vg = &g_qkv[t * 3 + 2][(size_t)bp * NN][0];
    uint32_t ks_u = smem_u32(Ks), vs_u = smem_u32(Vs);
    for (int i = tid; i < 512 * 8; i += 512) {
        int m = i >> 3, j = i & 7;
        cp16(ks_u + (m * 32 + j * 4) * 4, Kg + (size_t)m * DM + h * DK + j * 4);
        cp16(vs_u + (m * 32 + j * 4) * 4, Vg + (size_t)m * DM + h * DK + j * 4);
    }
    CP_COMMIT(); CP_WAIT0();
    __syncthreads();

    int rk = tid;
    int n = g_rowOfRank[t][rk];
    int gn = bp * NN + n;
    int rot = tid & 7;
    float4 qr[8];
    const float* Qg = &g_qkv[t * 3 + 0][gn][h * DK];
    #pragma unroll
    for (int j = 0; j < 8; j++) {
        int jj = (j + rot) & 7;
        qr[j] = *(const float4*)(Qg + jj * 4);
    }
    int cnt = g_nnzR[t][rk];
    float Z = 0.f;
    float4 av[8];
    #pragma unroll
    for (int j = 0; j < 8; j++) av[j] = make_float4(0.f, 0.f, 0.f, 0.f);
    const float scale = 0.17677669529663687f;   // 1/sqrt(32)

    int i = 0;
    for (; i + 1 < cnt; i += 2) {
        int   m0 = g_colsT[t][i][rk],     m1 = g_colsT[t][i + 1][rk];
        float t0 = g_valsT[t][i][rk],     t1 = g_valsT[t][i + 1][rk];
        const float* kb0 = Ks + m0 * 32;
        const float* kb1 = Ks + m1 * 32;
        float s0 = 0.f, s1 = 0.f;
        #pragma unroll
        for (int j = 0; j < 8; j++) {
            int jj = (j + rot) & 7;
            float4 a = *(const float4*)(kb0 + jj * 4);
            float4 b = *(const float4*)(kb1 + jj * 4);
            s0 += qr[j].x * a.x + qr[j].y * a.y + qr[j].z * a.z + qr[j].w * a.w;
            s1 += qr[j].x * b.x + qr[j].y * b.y + qr[j].z * b.z + qr[j].w * b.w;
        }
        float e0 = __expf(s0 * scale);
        float e1 = __expf(s1 * scale);
        Z += e0 + e1;
        float w0 = t0 * e0, w1 = t1 * e1;
        const float* vb0 = Vs + m0 * 32;
        const float* vb1 = Vs + m1 * 32;
        #pragma unroll
        for (int j = 0; j < 8; j++) {
            int jj = (j + rot) & 7;
            float4 a = *(const float4*)(vb0 + jj * 4);
            float4 b = *(const float4*)(vb1 + jj * 4);
            av[j].x += w0 * a.x + w1 * b.x;
            av[j].y += w0 * a.y + w1 * b.y;
            av[j].z += w0 * a.z + w1 * b.z;
            av[j].w += w0 * a.w + w1 * b.w;
        }
    }
    if (i < cnt) {
        int   m0 = g_colsT[t][i][rk];
        float t0 = g_valsT[t][i][rk];
        const float* kb0 = Ks + m0 * 32;
        float s0 = 0.f;
        #pragma unroll
        for (int j = 0; j < 8; j++) {
            int jj = (j + rot) & 7;
            float4 a = *(const float4*)(kb0 + jj * 4);
            s0 += qr[j].x * a.x + qr[j].y * a.y + qr[j].z * a.z + qr[j].w * a.w;
        }
        float e0 = __expf(s0 * scale);
        Z += e0;
        float w0 = t0 * e0;
        const float* vb0 = Vs + m0 * 32;
        #pragma unroll
        for (int j = 0; j < 8; j++) {
            int jj = (j + rot) & 7;
            float4 a = *(const float4*)(vb0 + jj * 4);
            av[j].x += w0 * a.x; av[j].y += w0 * a.y;
            av[j].z += w0 * a.z; av[j].w += w0 * a.w;
        }
    }
    float inv = 1.f / Z;
    float* out = &g_attn[t][gn][h * DK];
    #pragma unroll
    for (int j = 0; j < 8; j++) {
        int jj = (j + rot) & 7;
        float4 v = make_float4(av[j].x * inv, av[j].y * inv, av[j].z * inv, av[j].w * inv);
        *(float4*)(out + jj * 4) = v;
    }
}

// ===========================================================================
// Kernel 4: output projection via tf32 mma.sync (K=384 = 3 accumulated
// chunks), 512 threads / 16 warps, cp.async staging, fused residual + LN.
// ===========================================================================
__global__ void __launch_bounds__(512, 1)
outproj_mma_kernel(const float* __restrict__ X,
                   const float* __restrict__ Wo,
                   const float* __restrict__ gamma,
                   const float* __restrict__ beta,
                   float* __restrict__ out) {
    extern __shared__ uint32_t sm[];
    uint32_t* As = sm;                 // [128][LDP]
    uint32_t* Ws = sm + 128 * LDP;     // [128][LDP]
    float* Ys = (float*)sm;            // reuse As after GEMM
    int tid = threadIdx.x, lane = tid & 31, wid = tid >> 5;
    int mw = wid & 3, nw = wid >> 2;
    int g = lane >> 2, q = lane & 3;
    int row0 = blockIdx.x * 128;

    uint32_t as_u = smem_u32(As), ws_u = smem_u32(Ws);
    const uint32_t* abase = As + (mw * 32 + g) * LDP + q;
    const uint32_t* bbase = Ws + (nw * 32 + g) * LDP + q;

    float acc[2][4][4];
    #pragma unroll
    for (int t2 = 0; t2 < 2; t2++)
        #pragma unroll
        for (int j = 0; j < 4; j++)
            #pragma unroll
            for (int e = 0; e < 4; e++) acc[t2][j][e] = 0.f;

    for (int t = 0; t < NT; t++) {
        __syncthreads();
        for (int i = tid; i < 128 * 32; i += 512) {
            int r = i >> 5, k = (i & 31) << 2;
            cp16(as_u + (r * LDP + k) * 4, &g_attn[t][row0 + r][k]);
            cp16(ws_u + (r * LDP + k) * 4, Wo + (size_t)r * (NT * DM) + t * DM + k);
        }
        CP_COMMIT(); CP_WAIT0();
        __syncthreads();
        #pragma unroll 4
        for (int ks = 0; ks < 16; ks++) {
            int k0 = ks * 8;
            uint32_t a[2][4];
            #pragma unroll
            for (int t2 = 0; t2 < 2; t2++) {
                const uint32_t* ap = abase + t2 * 16 * LDP + k0;
                a[t2][0] = ap[0]; a[t2][1] = ap[8 * LDP];
                a[t2][2] = ap[4]; a[t2][3] = ap[8 * LDP + 4];
            }
            #pragma unroll
            for (int j = 0; j < 4; j++) {
                const uint32_t* bp = bbase + j * 8 * LDP + k0;
                uint32_t b[2]; b[0] = bp[0]; b[1] = bp[4];
                mma8(acc[0][j], a[0], b);
                mma8(acc[1][j], a[1], b);
            }
        }
    }
    __syncthreads();
    #pragma unroll
    for (int t2 = 0; t2 < 2; t2++) {
        int r = mw * 32 + t2 * 16 + g;
        #pragma unroll
        for (int j = 0; j < 4; j++) {
            int c = nw * 32 + j * 8 + q * 2;
            *(float2*)(Ys + r * LDP + c)       = make_float2(acc[t2][j][0], acc[t2][j][1]);
            *(float2*)(Ys + (r + 8) * LDP + c) = make_float2(acc[t2][j][2], acc[t2][j][3]);
        }
    }
    __syncthreads();
    for (int r = wid; r < 128; r += 16) {
        float4 y  = *(float4*)(Ys + r * LDP + lane * 4);
        float4 xv = *(const float4*)(X + (size_t)(row0 + r) * DM + lane * 4);
        float v0 = y.x + xv.x, v1 = y.y + xv.y, v2 = y.z + xv.z, v3 = y.w + xv.w;
        float s  = v0 + v1 + v2 + v3;
        float s2 = v0 * v0 + v1 * v1 + v2 * v2 + v3 * v3;
        #pragma unroll
        for (int off = 16; off; off >>= 1) {
            s  += __shfl_xor_sync(0xffffffffu, s,  off);
            s2 += __shfl_xor_sync(0xffffffffu, s2, off);
        }
        float mu = s * (1.f / DM);
        float var = s2 * (1.f / DM) - mu * mu;
        float rs = rsqrtf(var + 1e-5f);
        float4 gv = *(const float4*)(gamma + lane * 4);
        float4 bv = *(const float4*)(beta + lane * 4);
        float4 res = make_float4((v0 - mu) * rs * gv.x + bv.x,
                                 (v1 - mu) * rs * gv.y + bv.y,
                                 (v2 - mu) * rs * gv.z + bv.z,
                                 (v3 - mu) * rs * gv.w + bv.w);
        *(float4*)(out + (size_t)(row0 + r) * DM + lane * 4) = res;
    }
}

// ===========================================================================
extern "C" void kernel_launch(void* const* d_in, const int* in_sizes, int n_in,
                              void* d_out, int out_size) {
    const float* inputs = (const float*)d_in[0];
    const float* tm     = (const float*)d_in[2];
    const float* Wq     = (const float*)d_in[3];
    const float* Wk     = (const float*)d_in[4];
    const float* Wv     = (const float*)d_in[5];
    const float* Wo     = (const float*)d_in[6];
    const float* gamma  = (const float*)d_in[7];
    const float* beta   = (const float*)d_in[8];
    float* out = (float*)d_out;

    int smem_qkv  = 3 * 128 * LDP * (int)sizeof(float);   // 202752
    int smem_attn = 2 * 512 * 32 * (int)sizeof(float);    // 131072
    int smem_out  = 2 * 128 * LDP * (int)sizeof(float);   // 135168
    cudaFuncSetAttribute(qkv_mma_kernel,     cudaFuncAttributeMaxDynamicSharedMemorySize, smem_qkv);
    cudaFuncSetAttribute(attn_kernel,        cudaFuncAttributeMaxDynamicSharedMemorySize, smem_attn);
    cudaFuncSetAttribute(outproj_mma_kernel, cudaFuncAttributeMaxDynamicSharedMemorySize, smem_out);

    count_kernel<<<(NT * NN * 32 + 255) / 256, 256>>>(tm);
    rank_kernel<<<NT, NN>>>();
    fill_kernel<<<(NT * NN * 32 + 255) / 256, 256>>>(tm);
    qkv_mma_kernel<<<NROWS / 128, 512, smem_qkv>>>(inputs, Wq, Wk, Wv);
    attn_kernel<<<dim3(NH, NT * NB * NP), 512, smem_attn>>>();
    outproj_mma_kernel<<<NROWS / 128, 512, smem_out>>>(inputs, Wo, gamma, beta, out);
}

// round 7
// speedup vs baseline: 1.1492x; 1.1492x over previous
#include <cuda_runtime.h>
#include <cuda_fp16.h>
#include <math.h>
#include <stdint.h>

#define NB 4
#define NP 8
#define NN 512
#define DM 128
#define NH 4
#define DK 32
#define NT 3
#define NROWS (NB*NP*NN)     // 16384
#define MAXNNZ 128
#define LDP 132              // smem row stride (floats) for GEMM tiles
#define ALDW 20              // attn smem row stride in uint32 (half2) units

// Scratch (device globals)
__device__ float g_qkv[9][NROWS][DM];    // [t*3 + {Q,K,V}][row][d]
__device__ float g_attn[NT][NROWS][DM];  // per-t attention output
__device__ int   g_nnz[NT][NN];
__device__ int   g_colsT[NT][MAXNNZ][NN];   // [t][i][n] -> coalesced over n
__device__ float g_valsT[NT][MAXNNZ][NN];

__constant__ int c_which[NT] = {0, 1, 3};

// ---------------------------------------------------------------------------
__device__ __forceinline__ uint32_t f2tf32(float f) {
    uint32_t r; asm("cvt.rna.tf32.f32 %0, %1;" : "=r"(r) : "f"(f)); return r;
}
__device__ __forceinline__ uint32_t pack_h2(float a, float b) {
    __half2 h = __floats2half2_rn(a, b);
    return *(uint32_t*)&h;
}
// m16n8k8 tf32 MMA, D += A*B (row x col)
__device__ __forceinline__ void mma8(float d[4], const uint32_t a[4], const uint32_t b[2]) {
    asm volatile("mma.sync.aligned.m16n8k8.row.col.f32.tf32.tf32.f32 "
        "{%0,%1,%2,%3}, {%4,%5,%6,%7}, {%8,%9}, {%0,%1,%2,%3};"
        : "+f"(d[0]), "+f"(d[1]), "+f"(d[2]), "+f"(d[3])
        : "r"(a[0]), "r"(a[1]), "r"(a[2]), "r"(a[3]), "r"(b[0]), "r"(b[1]));
}

// ===========================================================================
// Kernel 1: build transposed CSR of the selected transition matrices.
// Warp per row n; ballot compaction; [t][i][n] layout (coalesced over n).
// ===========================================================================
__global__ void build_csr_kernel(const float* __restrict__ tmall) {
    int wg   = (blockIdx.x * blockDim.x + threadIdx.x) >> 5;
    int lane = threadIdx.x & 31;
    if (wg >= NT * NN) return;
    int t = wg / NN, n = wg % NN;
    const float* row = tmall + ((size_t)c_which[t] * NN + n) * NN;
    int cnt = 0;
    for (int base = 0; base < NN; base += 32) {
        float v = row[base + lane];
        unsigned b = __ballot_sync(0xffffffffu, v != 0.0f);
        if (v != 0.0f) {
            int pos = cnt + __popc(b & ((1u << lane) - 1u));
            if (pos < MAXNNZ) { g_colsT[t][pos][n] = base + lane; g_valsT[t][pos][n] = v; }
        }
        cnt += __popc(b);
    }
    if (lane == 0) g_nnz[t][n] = cnt < MAXNNZ ? cnt : MAXNNZ;
}

// ===========================================================================
// Kernel 2: QKV projections via tf32 mma.sync. 128-row tiles, 512 threads /
// 16 warps (4x4 grid of 32x32 tiles); 9 weight slots, W double-buffered.
// y[r][c] = sum_k X[r][k] * W[c][k]
// ===========================================================================
__global__ void __launch_bounds__(512, 1)
qkv_mma_kernel(const float* __restrict__ X,
               const float* __restrict__ Wq,
               const float* __restrict__ Wk,
               const float* __restrict__ Wv) {
    extern __shared__ uint32_t sm[];
    uint32_t* Xs = sm;                          // [128][LDP]
    uint32_t* Wsb0 = sm + 128 * LDP;
    uint32_t* Wsb1 = sm + 2 * 128 * LDP;
    int tid = threadIdx.x, lane = tid & 31, wid = tid >> 5;
    int mw = wid & 3, nw = wid >> 2;
    int g = lane >> 2, q = lane & 3;
    int row0 = blockIdx.x * 128;

    for (int i = tid; i < 128 * 32; i += 512) {
        int r = i >> 5, k = (i & 31) << 2;
        float4 v = *(const float4*)(X + (size_t)(row0 + r) * DM + k);
        uint32_t* d = Xs + r * LDP + k;
        d[0] = f2tf32(v.x); d[1] = f2tf32(v.y); d[2] = f2tf32(v.z); d[3] = f2tf32(v.w);
    }
    const float* Wbase[3] = {Wq, Wk, Wv};
    for (int i = tid; i < 128 * 32; i += 512) {
        int r = i >> 5, k = (i & 31) << 2;
        float4 v = *(const float4*)(Wbase[0] + (size_t)r * DM + k);
        uint32_t* d = Wsb0 + r * LDP + k;
        d[0] = f2tf32(v.x); d[1] = f2tf32(v.y); d[2] = f2tf32(v.z); d[3] = f2tf32(v.w);
    }
    __syncthreads();

    const uint32_t* abase = Xs + (mw * 32 + g) * LDP + q;

    for (int slot = 0; slot < 9; slot++) {
        if (slot < 8) {
            int ns = slot + 1;
            const float* W = Wbase[ns % 3] + (size_t)(ns / 3) * DM * DM;
            uint32_t* dst = (ns & 1) ? Wsb1 : Wsb0;
            for (int i = tid; i < 128 * 32; i += 512) {
                int r = i >> 5, k = (i & 31) << 2;
                float4 v = *(const float4*)(W + (size_t)r * DM + k);
                uint32_t* d = dst + r * LDP + k;
                d[0] = f2tf32(v.x); d[1] = f2tf32(v.y); d[2] = f2tf32(v.z); d[3] = f2tf32(v.w);
            }
        }
        const uint32_t* bbase = ((slot & 1) ? Wsb1 : Wsb0) + (nw * 32 + g) * LDP + q;

        float acc[2][4][4];
        #pragma unroll
        for (int t2 = 0; t2 < 2; t2++)
            #pragma unroll
            for (int j = 0; j < 4; j++)
                #pragma unroll
                for (int e = 0; e < 4; e++) acc[t2][j][e] = 0.f;

        #pragma unroll 4
        for (int ks = 0; ks < 16; ks++) {
            int k0 = ks * 8;
            uint32_t a[2][4];
            #pragma unroll
            for (int t2 = 0; t2 < 2; t2++) {
                const uint32_t* ap = abase + t2 * 16 * LDP + k0;
                a[t2][0] = ap[0]; a[t2][1] = ap[8 * LDP];
                a[t2][2] = ap[4]; a[t2][3] = ap[8 * LDP + 4];
            }
            #pragma unroll
            for (int j = 0; j < 4; j++) {
                const uint32_t* bp = bbase + j * 8 * LDP + k0;
                uint32_t b[2]; b[0] = bp[0]; b[1] = bp[4];
                mma8(acc[0][j], a[0], b);
                mma8(acc[1][j], a[1], b);
            }
        }
        float* out = &g_qkv[slot][row0][0];
        #pragma unroll
        for (int t2 = 0; t2 < 2; t2++) {
            int r = mw * 32 + t2 * 16 + g;
            #pragma unroll
            for (int j = 0; j < 4; j++) {
                int c = nw * 32 + j * 8 + q * 2;
                *(float2*)(out + (size_t)r * DM + c)       = make_float2(acc[t2][j][0], acc[t2][j][1]);
                *(float2*)(out + (size_t)(r + 8) * DM + c) = make_float2(acc[t2][j][2], acc[t2][j][3]);
            }
        }
        __syncthreads();
    }
}

// ===========================================================================
// Kernel 3: sparse-masked attention, fp16 K/V in SMEM (fp32 accumulation).
// Block = (t,bp,h), 256 threads, 2 CTAs/SM; each thread does 2 query rows.
// Row stride ALDW=20 uint32 -> m*20 mod 32 cycles all 8 four-bank groups,
// so the CSR's random m spreads LDS banks. Direct exp (scores ~N(0,1)).
// ===========================================================================
__global__ void __launch_bounds__(256, 2)
attn_kernel() {
    extern __shared__ uint32_t smw[];
    uint32_t* Ks = smw;                  // [512][ALDW] half2 units
    uint32_t* Vs = smw + 512 * ALDW;
    int tid = threadIdx.x;
    int h = blockIdx.x;
    int t = blockIdx.y >> 5, bp = blockIdx.y & 31;

    const float* Kg = &g_qkv[t * 3 + 1][(size_t)bp * NN][0];
    const float* Vg = &g_qkv[t * 3 + 2][(size_t)bp * NN][0];
    // stage K/V as half2: row m, chunk c (8 dims) -> words m*ALDW + 4c .. +3
    for (int i = tid; i < 512 * 4; i += 256) {
        int m = i >> 2, c = i & 3;
        const float4* kp = (const float4*)(Kg + (size_t)m * DM + h * DK + c * 8);
        float4 k0 = kp[0], k1 = kp[1];
        uint4 pk = make_uint4(pack_h2(k0.x, k0.y), pack_h2(k0.z, k0.w),
                              pack_h2(k1.x, k1.y), pack_h2(k1.z, k1.w));
        *(uint4*)(Ks + m * ALDW + c * 4) = pk;
        const float4* vp = (const float4*)(Vg + (size_t)m * DM + h * DK + c * 8);
        float4 v0 = vp[0], v1 = vp[1];
        uint4 pv = make_uint4(pack_h2(v0.x, v0.y), pack_h2(v0.z, v0.w),
                              pack_h2(v1.x, v1.y), pack_h2(v1.z, v1.w));
        *(uint4*)(Vs + m * ALDW + c * 4) = pv;
    }
    __syncthreads();

    const float scale = 0.17677669529663687f;   // 1/sqrt(32)

    for (int n = tid; n < NN; n += 256) {
        int gn = bp * NN + n;
        float q[32];
        const float* Qg = &g_qkv[t * 3 + 0][gn][h * DK];
        #pragma unroll
        for (int c4 = 0; c4 < 32; c4 += 4) {
            float4 v = *(const float4*)(Qg + c4);
            q[c4] = v.x; q[c4 + 1] = v.y; q[c4 + 2] = v.z; q[c4 + 3] = v.w;
        }
        int cnt = g_nnz[t][n];
        float Z = 0.f;
        float av[32];
        #pragma unroll
        for (int c = 0; c < 32; c++) av[c] = 0.f;

        for (int i = 0; i < cnt; i++) {
            int m = g_colsT[t][i][n];        // coalesced over n
            float tv = g_valsT[t][i][n];
            const uint32_t* kb = Ks + m * ALDW;
            float s = 0.f;
            #pragma unroll
            for (int c = 0; c < 4; c++) {
                uint4 kk = *(const uint4*)(kb + c * 4);
                float2 f;
                f = __half22float2(*(__half2*)&kk.x); s += q[c*8+0]*f.x + q[c*8+1]*f.y;
                f = __half22float2(*(__half2*)&kk.y); s += q[c*8+2]*f.x + q[c*8+3]*f.y;
                f = __half22float2(*(__half2*)&kk.z); s += q[c*8+4]*f.x + q[c*8+5]*f.y;
                f = __half22float2(*(__half2*)&kk.w); s += q[c*8+6]*f.x + q[c*8+7]*f.y;
            }
            float e = __expf(s * scale);
            Z += e;
            float we = tv * e;
            const uint32_t* vb = Vs + m * ALDW;
            #pragma unroll
            for (int c = 0; c < 4; c++) {
                uint4 vv = *(const uint4*)(vb + c * 4);
                float2 f;
                f = __half22float2(*(__half2*)&vv.x); av[c*8+0] += we*f.x; av[c*8+1] += we*f.y;
                f = __half22float2(*(__half2*)&vv.y); av[c*8+2] += we*f.x; av[c*8+3] += we*f.y;
                f = __half22float2(*(__half2*)&vv.z); av[c*8+4] += we*f.x; av[c*8+5] += we*f.y;
                f = __half22float2(*(__half2*)&vv.w); av[c*8+6] += we*f.x; av[c*8+7] += we*f.y;
            }
        }
        float inv = 1.f / Z;
        float* outp = &g_attn[t][gn][h * DK];
        #pragma unroll
        for (int c4 = 0; c4 < 32; c4 += 4) {
            float4 v = make_float4(av[c4] * inv, av[c4+1] * inv,
                                   av[c4+2] * inv, av[c4+3] * inv);
            *(float4*)(outp + c4) = v;
        }
    }
}

// ===========================================================================
// Kernel 4: output projection via tf32 mma.sync (K=384 = 3 accumulated
// chunks), 512 threads / 16 warps, fused residual + warp-per-row LayerNorm.
// ===========================================================================
__global__ void __launch_bounds__(512, 1)
outproj_mma_kernel(const float* __restrict__ X,
                   const float* __restrict__ Wo,
                   const float* __restrict__ gamma,
                   const float* __restrict__ beta,
                   float* __restrict__ out) {
    extern __shared__ uint32_t sm[];
    uint32_t* As = sm;                 // [128][LDP]
    uint32_t* Ws = sm + 128 * LDP;     // [128][LDP]
    float* Ys = (float*)sm;            // reuse As after GEMM
    int tid = threadIdx.x, lane = tid & 31, wid = tid >> 5;
    int mw = wid & 3, nw = wid >> 2;
    int g = lane >> 2, q = lane & 3;
    int row0 = blockIdx.x * 128;

    const uint32_t* abase = As + (mw * 32 + g) * LDP + q;
    const uint32_t* bbase = Ws + (nw * 32 + g) * LDP + q;

    float acc[2][4][4];
    #pragma unroll
    for (int t2 = 0; t2 < 2; t2++)
        #pragma unroll
        for (int j = 0; j < 4; j++)
            #pragma unroll
            for (int e = 0; e < 4; e++) acc[t2][j][e] = 0.f;

    for (int t = 0; t < NT; t++) {
        __syncthreads();
        for (int i = tid; i < 128 * 32; i += 512) {
            int r = i >> 5, k = (i & 31) << 2;
            float4 a = *(const float4*)(&g_attn[t][row0 + r][k]);
            uint32_t* d = As + r * LDP + k;
            d[0] = f2tf32(a.x); d[1] = f2tf32(a.y); d[2] = f2tf32(a.z); d[3] = f2tf32(a.w);
            float4 w = *(const float4*)(Wo + (size_t)r * (NT * DM) + t * DM + k);
            uint32_t* d2 = Ws + r * LDP + k;
            d2[0] = f2tf32(w.x); d2[1] = f2tf32(w.y); d2[2] = f2tf32(w.z); d2[3] = f2tf32(w.w);
        }
        __syncthreads();
        #pragma unroll 4
        for (int ks = 0; ks < 16; ks++) {
            int k0 = ks * 8;
            uint32_t a[2][4];
            #pragma unroll
            for (int t2 = 0; t2 < 2; t2++) {
                const uint32_t* ap = abase + t2 * 16 * LDP + k0;
                a[t2][0] = ap[0]; a[t2][1] = ap[8 * LDP];
                a[t2][2] = ap[4]; a[t2][3] = ap[8 * LDP + 4];
            }
            #pragma unroll
            for (int j = 0; j < 4; j++) {
                const uint32_t* bp = bbase + j * 8 * LDP + k0;
                uint32_t b[2]; b[0] = bp[0]; b[1] = bp[4];
                mma8(acc[0][j], a[0], b);
                mma8(acc[1][j], a[1], b);
            }
        }
    }
    __syncthreads();
    #pragma unroll
    for (int t2 = 0; t2 < 2; t2++) {
        int r = mw * 32 + t2 * 16 + g;
        #pragma unroll
        for (int j = 0; j < 4; j++) {
            int c = nw * 32 + j * 8 + q * 2;
            *(float2*)(Ys + r * LDP + c)       = make_float2(acc[t2][j][0], acc[t2][j][1]);
            *(float2*)(Ys + (r + 8) * LDP + c) = make_float2(acc[t2][j][2], acc[t2][j][3]);
        }
    }
    __syncthreads();
    for (int r = wid; r < 128; r += 16) {
        float4 y  = *(float4*)(Ys + r * LDP + lane * 4);
        float4 xv = *(const float4*)(X + (size_t)(row0 + r) * DM + lane * 4);
        float v0 = y.x + xv.x, v1 = y.y + xv.y, v2 = y.z + xv.z, v3 = y.w + xv.w;
        float s  = v0 + v1 + v2 + v3;
        float s2 = v0 * v0 + v1 * v1 + v2 * v2 + v3 * v3;
        #pragma unroll
        for (int off = 16; off; off >>= 1) {
            s  += __shfl_xor_sync(0xffffffffu, s,  off);
            s2 += __shfl_xor_sync(0xffffffffu, s2, off);
        }
        float mu = s * (1.f / DM);
        float var = s2 * (1.f / DM) - mu * mu;
        float rs = rsqrtf(var + 1e-5f);
        float4 gv = *(const float4*)(gamma + lane * 4);
        float4 bv = *(const float4*)(beta + lane * 4);
        float4 res = make_float4((v0 - mu) * rs * gv.x + bv.x,
                                 (v1 - mu) * rs * gv.y + bv.y,
                                 (v2 - mu) * rs * gv.z + bv.z,
                                 (v3 - mu) * rs * gv.w + bv.w);
        *(float4*)(out + (size_t)(row0 + r) * DM + lane * 4) = res;
    }
}

// ===========================================================================
extern "C" void kernel_launch(void* const* d_in, const int* in_sizes, int n_in,
                              void* d_out, int out_size) {
    const float* inputs = (const float*)d_in[0];
    const float* tm     = (const float*)d_in[2];
    const float* Wq     = (const float*)d_in[3];
    const float* Wk     = (const float*)d_in[4];
    const float* Wv     = (const float*)d_in[5];
    const float* Wo     = (const float*)d_in[6];
    const float* gamma  = (const float*)d_in[7];
    const float* beta   = (const float*)d_in[8];
    float* out = (float*)d_out;

    int smem_qkv  = 3 * 128 * LDP * (int)sizeof(float);   // 202752
    int smem_attn = 2 * 512 * ALDW * (int)sizeof(uint32_t); // 81920
    int smem_out  = 2 * 128 * LDP * (int)sizeof(float);   // 135168
    cudaFuncSetAttribute(qkv_mma_kernel,     cudaFuncAttributeMaxDynamicSharedMemorySize, smem_qkv);
    cudaFuncSetAttribute(attn_kernel,        cudaFuncAttributeMaxDynamicSharedMemorySize, smem_attn);
    cudaFuncSetAttribute(outproj_mma_kernel, cudaFuncAttributeMaxDynamicSharedMemorySize, smem_out);

    build_csr_kernel<<<(NT * NN * 32 + 255) / 256, 256>>>(tm);
    qkv_mma_kernel<<<NROWS / 128, 512, smem_qkv>>>(inputs, Wq, Wk, Wv);
    attn_kernel<<<dim3(NH, NT * NB * NP), 256, smem_attn>>>();
    outproj_mma_kernel<<<NROWS / 128, 512, smem_out>>>(inputs, Wo, gamma, beta, out);
}

// round 8
// speedup vs baseline: 1.4554x; 1.2665x over previous
#include <cuda_runtime.h>
#include <math.h>
#include <stdint.h>

#define NB 4
#define NP 8
#define NN 512
#define DM 128
#define NH 4
#define DK 32
#define NT 3
#define NROWS (NB*NP*NN)     // 16384
#define MAXNNZ 128
#define LDP 132              // smem row stride (floats) for GEMM tiles

// Scratch (device globals)
__device__ float g_qkv[9][NROWS][DM];    // [t*3 + {Q,K,V}][row][d]
__device__ float g_attn[NT][NROWS][DM];  // per-t attention output
__device__ int   g_nnz[NT][NN];
__device__ int   g_colsT[NT][MAXNNZ][NN];   // [t][i][n] -> coalesced over n
__device__ float g_valsT[NT][MAXNNZ][NN];

__constant__ int c_which[NT] = {0, 1, 3};

// ---------------------------------------------------------------------------
__device__ __forceinline__ uint32_t smem_u32(const void* p) {
    uint32_t a;
    asm("{ .reg .u64 t; cvta.to.shared.u64 t, %1; cvt.u32.u64 %0, t; }" : "=r"(a) : "l"(p));
    return a;
}
__device__ __forceinline__ void cp16(uint32_t dst, const void* src) {
    asm volatile("cp.async.ca.shared.global [%0], [%1], 16;" :: "r"(dst), "l"(src));
}
#define CP_COMMIT() asm volatile("cp.async.commit_group;" ::: "memory")
#define CP_WAIT0()  asm volatile("cp.async.wait_group 0;" ::: "memory")

__device__ __forceinline__ uint32_t f2tf32(float f) {
    uint32_t r; asm("cvt.rna.tf32.f32 %0, %1;" : "=r"(r) : "f"(f)); return r;
}
// m16n8k8 tf32 MMA, D += A*B (row x col). Raw fp32 bits are valid tf32
// operands (HW ignores low mantissa bits -> truncation rounding).
__device__ __forceinline__ void mma8(float d[4], const uint32_t a[4], const uint32_t b[2]) {
    asm volatile("mma.sync.aligned.m16n8k8.row.col.f32.tf32.tf32.f32 "
        "{%0,%1,%2,%3}, {%4,%5,%6,%7}, {%8,%9}, {%0,%1,%2,%3};"
        : "+f"(d[0]), "+f"(d[1]), "+f"(d[2]), "+f"(d[3])
        : "r"(a[0]), "r"(a[1]), "r"(a[2]), "r"(a[3]), "r"(b[0]), "r"(b[1]));
}

// ===========================================================================
// Kernel 1: build transposed CSR of the selected transition matrices.
// Warp per row n; ballot compaction; [t][i][n] layout (coalesced over n).
// ===========================================================================
__global__ void build_csr_kernel(const float* __restrict__ tmall) {
    int wg   = (blockIdx.x * blockDim.x + threadIdx.x) >> 5;
    int lane = threadIdx.x & 31;
    if (wg >= NT * NN) return;
    int t = wg / NN, n = wg % NN;
    const float* row = tmall + ((size_t)c_which[t] * NN + n) * NN;
    int cnt = 0;
    for (int base = 0; base < NN; base += 32) {
        float v = row[base + lane];
        unsigned b = __ballot_sync(0xffffffffu, v != 0.0f);
        if (v != 0.0f) {
            int pos = cnt + __popc(b & ((1u << lane) - 1u));
            if (pos < MAXNNZ) { g_colsT[t][pos][n] = base + lane; g_valsT[t][pos][n] = v; }
        }
        cnt += __popc(b);
    }
    if (lane == 0) g_nnz[t][n] = cnt < MAXNNZ ? cnt : MAXNNZ;
}

// ===========================================================================
// Kernel 2: QKV projections via tf32 mma.sync, parallelized over
// (slot, row-tile): grid = (256 tiles, 9 slots). Each block stages one
// 64-row X tile + one full W with cp.async, computes once, stores.
// 256 threads / 8 warps (2m x 4n grid of 32x32 tiles), 2 CTAs/SM.
// ===========================================================================
__global__ void __launch_bounds__(256, 2)
qkv_mma_kernel(const float* __restrict__ X,
               const float* __restrict__ Wq,
               const float* __restrict__ Wk,
               const float* __restrict__ Wv) {
    extern __shared__ uint32_t sm[];
    uint32_t* Xs = sm;                // [64][LDP]
    uint32_t* Ws = sm + 64 * LDP;     // [128][LDP]
    int tid = threadIdx.x, lane = tid & 31, wid = tid >> 5;
    int mw = wid & 1, nw = wid >> 1;
    int g = lane >> 2, q = lane & 3;
    int slot = blockIdx.y;
    int row0 = blockIdx.x * 64;

    const float* Wb[3] = {Wq, Wk, Wv};
    const float* W = Wb[slot % 3] + (size_t)(slot / 3) * DM * DM;

    uint32_t xs_u = smem_u32(Xs), ws_u = smem_u32(Ws);
    for (int i = tid; i < 64 * 32; i += 256) {
        int r = i >> 5, k = (i & 31) << 2;
        cp16(xs_u + (r * LDP + k) * 4, X + (size_t)(row0 + r) * DM + k);
    }
    for (int i = tid; i < 128 * 32; i += 256) {
        int r = i >> 5, k = (i & 31) << 2;
        cp16(ws_u + (r * LDP + k) * 4, W + (size_t)r * DM + k);
    }
    CP_COMMIT(); CP_WAIT0();
    __syncthreads();

    const uint32_t* abase = Xs + (mw * 32 + g) * LDP + q;
    const uint32_t* bbase = Ws + (nw * 32 + g) * LDP + q;

    float acc[2][4][4];
    #pragma unroll
    for (int t2 = 0; t2 < 2; t2++)
        #pragma unroll
        for (int j = 0; j < 4; j++)
            #pragma unroll
            for (int e = 0; e < 4; e++) acc[t2][j][e] = 0.f;

    #pragma unroll 4
    for (int ks = 0; ks < 16; ks++) {
        int k0 = ks * 8;
        uint32_t a[2][4];
        #pragma unroll
        for (int t2 = 0; t2 < 2; t2++) {
            const uint32_t* ap = abase + t2 * 16 * LDP + k0;
            a[t2][0] = ap[0]; a[t2][1] = ap[8 * LDP];
            a[t2][2] = ap[4]; a[t2][3] = ap[8 * LDP + 4];
        }
        #pragma unroll
        for (int j = 0; j < 4; j++) {
            const uint32_t* bp = bbase + j * 8 * LDP + k0;
            uint32_t b[2]; b[0] = bp[0]; b[1] = bp[4];
            mma8(acc[0][j], a[0], b);
            mma8(acc[1][j], a[1], b);
        }
    }
    float* out = &g_qkv[slot][row0][0];
    #pragma unroll
    for (int t2 = 0; t2 < 2; t2++) {
        int r = mw * 32 + t2 * 16 + g;
        #pragma unroll
        for (int j = 0; j < 4; j++) {
            int c = nw * 32 + j * 8 + q * 2;
            *(float2*)(out + (size_t)r * DM + c)       = make_float2(acc[t2][j][0], acc[t2][j][1]);
            *(float2*)(out + (size_t)(r + 8) * DM + c) = make_float2(acc[t2][j][2], acc[t2][j][3]);
        }
    }
}

// ===========================================================================
// Kernel 3: sparse-masked attention (exact R4 structure). Block = (t,bp,h),
// 512 threads, one per query row. K/V in SMEM stride-32 floats; lane-rotated
// float4 reads -> deterministic 4-phase crossbar (bank group depends only on
// rotated chunk index, not the random CSR column). Direct exp; coalesced
// transposed CSR.
// ===========================================================================
__global__ void __launch_bounds__(512, 1)
attn_kernel() {
    extern __shared__ float smf[];
    float* Ks = smf;               // [512][32]
    float* Vs = smf + 512 * 32;    // [512][32]
    int tid = threadIdx.x;
    int h = blockIdx.x;
    int t = blockIdx.y >> 5, bp = blockIdx.y & 31;

    const float* Kg = &g_qkv[t * 3 + 1][(size_t)bp * NN][0];
    const float* Vg = &g_qkv[t * 3 + 2][(size_t)bp * NN][0];
    for (int i = tid; i < 512 * 8; i += 512) {
        int m = i >> 3, j = i & 7;
        float4 kv = *(const float4*)(Kg + (size_t)m * DM + h * DK + j * 4);
        float4 vv = *(const float4*)(Vg + (size_t)m * DM + h * DK + j * 4);
        *(float4*)(Ks + m * 32 + j * 4) = kv;
        *(float4*)(Vs + m * 32 + j * 4) = vv;
    }
    __syncthreads();

    int n = tid;
    int gn = bp * NN + n;
    int rot = tid & 7;
    float4 qr[8];
    const float* Qg = &g_qkv[t * 3 + 0][gn][h * DK];
    #pragma unroll
    for (int j = 0; j < 8; j++) {
        int jj = (j + rot) & 7;
        qr[j] = *(const float4*)(Qg + jj * 4);
    }
    int cnt = g_nnz[t][n];
    float Z = 0.f;
    float4 av[8];
    #pragma unroll
    for (int j = 0; j < 8; j++) av[j] = make_float4(0.f, 0.f, 0.f, 0.f);
    const float scale = 0.17677669529663687f;   // 1/sqrt(32)

    for (int i = 0; i < cnt; i++) {
        int m = g_colsT[t][i][n];        // coalesced: lanes = consecutive n
        float tv = g_valsT[t][i][n];
        const float* kb = Ks + m * 32;
        float s = 0.f;
        #pragma unroll
        for (int j = 0; j < 8; j++) {
            int jj = (j + rot) & 7;
            float4 k4 = *(const float4*)(kb + jj * 4);
            s += qr[j].x * k4.x + qr[j].y * k4.y + qr[j].z * k4.z + qr[j].w * k4.w;
        }
        float e = __expf(s * scale);
        Z += e;
        float we = tv * e;
        const float* vb = Vs + m * 32;
        #pragma unroll
        for (int j = 0; j < 8; j++) {
            int jj = (j + rot) & 7;
            float4 v4 = *(const float4*)(vb + jj * 4);
            av[j].x += we * v4.x;
            av[j].y += we * v4.y;
            av[j].z += we * v4.z;
            av[j].w += we * v4.w;
        }
    }
    float inv = 1.f / Z;
    float* out = &g_attn[t][gn][h * DK];
    #pragma unroll
    for (int j = 0; j < 8; j++) {
        int jj = (j + rot) & 7;
        float4 v = make_float4(av[j].x * inv, av[j].y * inv, av[j].z * inv, av[j].w * inv);
        *(float4*)(out + jj * 4) = v;
    }
}

// ===========================================================================
// Kernel 4: output projection via tf32 mma.sync (K=384 = 3 accumulated
// chunks), 512 threads / 16 warps, fused residual + warp-per-row LayerNorm.
// ===========================================================================
__global__ void __launch_bounds__(512, 1)
outproj_mma_kernel(const float* __restrict__ X,
                   const float* __restrict__ Wo,
                   const float* __restrict__ gamma,
                   const float* __restrict__ beta,
                   float* __restrict__ out) {
    extern __shared__ uint32_t sm[];
    uint32_t* As = sm;                 // [128][LDP]
    uint32_t* Ws = sm + 128 * LDP;     // [128][LDP]
    float* Ys = (float*)sm;            // reuse As after GEMM
    int tid = threadIdx.x, lane = tid & 31, wid = tid >> 5;
    int mw = wid & 3, nw = wid >> 2;
    int g = lane >> 2, q = lane & 3;
    int row0 = blockIdx.x * 128;

    const uint32_t* abase = As + (mw * 32 + g) * LDP + q;
    const uint32_t* bbase = Ws + (nw * 32 + g) * LDP + q;

    float acc[2][4][4];
    #pragma unroll
    for (int t2 = 0; t2 < 2; t2++)
        #pragma unroll
        for (int j = 0; j < 4; j++)
            #pragma unroll
            for (int e = 0; e < 4; e++) acc[t2][j][e] = 0.f;

    for (int t = 0; t < NT; t++) {
        __syncthreads();
        for (int i = tid; i < 128 * 32; i += 512) {
            int r = i >> 5, k = (i & 31) << 2;
            float4 a = *(const float4*)(&g_attn[t][row0 + r][k]);
            uint32_t* d = As + r * LDP + k;
            d[0] = f2tf32(a.x); d[1] = f2tf32(a.y); d[2] = f2tf32(a.z); d[3] = f2tf32(a.w);
            float4 w = *(const float4*)(Wo + (size_t)r * (NT * DM) + t * DM + k);
            uint32_t* d2 = Ws + r * LDP + k;
            d2[0] = f2tf32(w.x); d2[1] = f2tf32(w.y); d2[2] = f2tf32(w.z); d2[3] = f2tf32(w.w);
        }
        __syncthreads();
        #pragma unroll 4
        for (int ks = 0; ks < 16; ks++) {
            int k0 = ks * 8;
            uint32_t a[2][4];
            #pragma unroll
            for (int t2 = 0; t2 < 2; t2++) {
                const uint32_t* ap = abase + t2 * 16 * LDP + k0;
                a[t2][0] = ap[0]; a[t2][1] = ap[8 * LDP];
                a[t2][2] = ap[4]; a[t2][3] = ap[8 * LDP + 4];
            }
            #pragma unroll
            for (int j = 0; j < 4; j++) {
                const uint32_t* bp = bbase + j * 8 * LDP + k0;
                uint32_t b[2]; b[0] = bp[0]; b[1] = bp[4];
                mma8(acc[0][j], a[0], b);
                mma8(acc[1][j], a[1], b);
            }
        }
    }
    __syncthreads();
    #pragma unroll
    for (int t2 = 0; t2 < 2; t2++) {
        int r = mw * 32 + t2 * 16 + g;
        #pragma unroll
        for (int j = 0; j < 4; j++) {
            int c = nw * 32 + j * 8 + q * 2;
            *(float2*)(Ys + r * LDP + c)       = make_float2(acc[t2][j][0], acc[t2][j][1]);
            *(float2*)(Ys + (r + 8) * LDP + c) = make_float2(acc[t2][j][2], acc[t2][j][3]);
        }
    }
    __syncthreads();
    for (int r = wid; r < 128; r += 16) {
        float4 y  = *(float4*)(Ys + r * LDP + lane * 4);
        float4 xv = *(const float4*)(X + (size_t)(row0 + r) * DM + lane * 4);
        float v0 = y.x + xv.x, v1 = y.y + xv.y, v2 = y.z + xv.z, v3 = y.w + xv.w;
        float s  = v0 + v1 + v2 + v3;
        float s2 = v0 * v0 + v1 * v1 + v2 * v2 + v3 * v3;
        #pragma unroll
        for (int off = 16; off; off >>= 1) {
            s  += __shfl_xor_sync(0xffffffffu, s,  off);
            s2 += __shfl_xor_sync(0xffffffffu, s2, off);
        }
        float mu = s * (1.f / DM);
        float var = s2 * (1.f / DM) - mu * mu;
        float rs = rsqrtf(var + 1e-5f);
        float4 gv = *(const float4*)(gamma + lane * 4);
        float4 bv = *(const float4*)(beta + lane * 4);
        float4 res = make_float4((v0 - mu) * rs * gv.x + bv.x,
                                 (v1 - mu) * rs * gv.y + bv.y,
                                 (v2 - mu) * rs * gv.z + bv.z,
                                 (v3 - mu) * rs * gv.w + bv.w);
        *(float4*)(out + (size_t)(row0 + r) * DM + lane * 4) = res;
    }
}

// ===========================================================================
extern "C" void kernel_launch(void* const* d_in, const int* in_sizes, int n_in,
                              void* d_out, int out_size) {
    const float* inputs = (const float*)d_in[0];
    const float* tm     = (const float*)d_in[2];
    const float* Wq     = (const float*)d_in[3];
    const float* Wk     = (const float*)d_in[4];
    const float* Wv     = (const float*)d_in[5];
    const float* Wo     = (const float*)d_in[6];
    const float* gamma  = (const float*)d_in[7];
    const float* beta   = (const float*)d_in[8];
    float* out = (float*)d_out;

    int smem_qkv  = (64 + 128) * LDP * (int)sizeof(float);  // 101376
    int smem_attn = 2 * 512 * 32 * (int)sizeof(float);      // 131072
    int smem_out  = 2 * 128 * LDP * (int)sizeof(float);     // 135168
    cudaFuncSetAttribute(qkv_mma_kernel,     cudaFuncAttributeMaxDynamicSharedMemorySize, smem_qkv);
    cudaFuncSetAttribute(attn_kernel,        cudaFuncAttributeMaxDynamicSharedMemorySize, smem_attn);
    cudaFuncSetAttribute(outproj_mma_kernel, cudaFuncAttributeMaxDynamicSharedMemorySize, smem_out);

    build_csr_kernel<<<(NT * NN * 32 + 255) / 256, 256>>>(tm);
    qkv_mma_kernel<<<dim3(NROWS / 64, 9), 256, smem_qkv>>>(inputs, Wq, Wk, Wv);
    attn_kernel<<<dim3(NH, NT * NB * NP), 512, smem_attn>>>();
    outproj_mma_kernel<<<NROWS / 128, 512, smem_out>>>(inputs, Wo, gamma, beta, out);
}

// round 9
// speedup vs baseline: 1.5603x; 1.0721x over previous
#include <cuda_runtime.h>
#include <cuda_fp16.h>
#include <math.h>
#include <stdint.h>

#define NB 4
#define NP 8
#define NN 512
#define DM 128
#define NH 4
#define DK 32
#define NT 3
#define NROWS (NB*NP*NN)     // 16384
#define MAXNNZ 128
#define LDP 132              // smem row stride (floats) for GEMM tiles

// Scratch (device globals). g_qkv is fp16 to halve intermediate HBM traffic.
__device__ __half g_qkv[9][NROWS][DM];   // [t*3 + {Q,K,V}][row][d]
__device__ float  g_attn[NT][NROWS][DM]; // per-t attention output (fp32)
__device__ int    g_nnz[NT][NN];
__device__ int    g_colsT[NT][MAXNNZ][NN];   // [t][i][n] -> coalesced over n
__device__ float  g_valsT[NT][MAXNNZ][NN];

__constant__ int c_which[NT] = {0, 1, 3};

// ---------------------------------------------------------------------------
__device__ __forceinline__ uint32_t smem_u32(const void* p) {
    uint32_t a;
    asm("{ .reg .u64 t; cvta.to.shared.u64 t, %1; cvt.u32.u64 %0, t; }" : "=r"(a) : "l"(p));
    return a;
}
__device__ __forceinline__ void cp16(uint32_t dst, const void* src) {
    asm volatile("cp.async.ca.shared.global [%0], [%1], 16;" :: "r"(dst), "l"(src));
}
#define CP_COMMIT() asm volatile("cp.async.commit_group;" ::: "memory")
#define CP_WAIT0()  asm volatile("cp.async.wait_group 0;" ::: "memory")

__device__ __forceinline__ uint32_t f2tf32(float f) {
    uint32_t r; asm("cvt.rna.tf32.f32 %0, %1;" : "=r"(r) : "f"(f)); return r;
}
__device__ __forceinline__ uint32_t pack_h2(float a, float b) {
    __half2 h = __floats2half2_rn(a, b);
    return *(uint32_t*)&h;
}
// m16n8k8 tf32 MMA, D += A*B (row x col)
__device__ __forceinline__ void mma8(float d[4], const uint32_t a[4], const uint32_t b[2]) {
    asm volatile("mma.sync.aligned.m16n8k8.row.col.f32.tf32.tf32.f32 "
        "{%0,%1,%2,%3}, {%4,%5,%6,%7}, {%8,%9}, {%0,%1,%2,%3};"
        : "+f"(d[0]), "+f"(d[1]), "+f"(d[2]), "+f"(d[3])
        : "r"(a[0]), "r"(a[1]), "r"(a[2]), "r"(a[3]), "r"(b[0]), "r"(b[1]));
}

// ===========================================================================
// Kernel 1: build transposed CSR of the selected transition matrices.
// ===========================================================================
__global__ void build_csr_kernel(const float* __restrict__ tmall) {
    int wg   = (blockIdx.x * blockDim.x + threadIdx.x) >> 5;
    int lane = threadIdx.x & 31;
    if (wg >= NT * NN) return;
    int t = wg / NN, n = wg % NN;
    const float* row = tmall + ((size_t)c_which[t] * NN + n) * NN;
    int cnt = 0;
    for (int base = 0; base < NN; base += 32) {
        float v = row[base + lane];
        unsigned b = __ballot_sync(0xffffffffu, v != 0.0f);
        if (v != 0.0f) {
            int pos = cnt + __popc(b & ((1u << lane) - 1u));
            if (pos < MAXNNZ) { g_colsT[t][pos][n] = base + lane; g_valsT[t][pos][n] = v; }
        }
        cnt += __popc(b);
    }
    if (lane == 0) g_nnz[t][n] = cnt < MAXNNZ ? cnt : MAXNNZ;
}

// ===========================================================================
// Kernel 2: QKV projections via tf32 mma.sync, grid = (256 tiles, 9 slots),
// 256 threads / 8 warps, 2 CTAs/SM, cp.async staging. Output stored fp16.
// ===========================================================================
__global__ void __launch_bounds__(256, 2)
qkv_mma_kernel(const float* __restrict__ X,
               const float* __restrict__ Wq,
               const float* __restrict__ Wk,
               const float* __restrict__ Wv) {
    extern __shared__ uint32_t sm[];
    uint32_t* Xs = sm;                // [64][LDP]
    uint32_t* Ws = sm + 64 * LDP;     // [128][LDP]
    int tid = threadIdx.x, lane = tid & 31, wid = tid >> 5;
    int mw = wid & 1, nw = wid >> 1;
    int g = lane >> 2, q = lane & 3;
    int slot = blockIdx.y;
    int row0 = blockIdx.x * 64;

    const float* Wb[3] = {Wq, Wk, Wv};
    const float* W = Wb[slot % 3] + (size_t)(slot / 3) * DM * DM;

    uint32_t xs_u = smem_u32(Xs), ws_u = smem_u32(Ws);
    for (int i = tid; i < 64 * 32; i += 256) {
        int r = i >> 5, k = (i & 31) << 2;
        cp16(xs_u + (r * LDP + k) * 4, X + (size_t)(row0 + r) * DM + k);
    }
    for (int i = tid; i < 128 * 32; i += 256) {
        int r = i >> 5, k = (i & 31) << 2;
        cp16(ws_u + (r * LDP + k) * 4, W + (size_t)r * DM + k);
    }
    CP_COMMIT(); CP_WAIT0();
    __syncthreads();

    const uint32_t* abase = Xs + (mw * 32 + g) * LDP + q;
    const uint32_t* bbase = Ws + (nw * 32 + g) * LDP + q;

    float acc[2][4][4];
    #pragma unroll
    for (int t2 = 0; t2 < 2; t2++)
        #pragma unroll
        for (int j = 0; j < 4; j++)
            #pragma unroll
            for (int e = 0; e < 4; e++) acc[t2][j][e] = 0.f;

    #pragma unroll 4
    for (int ks = 0; ks < 16; ks++) {
        int k0 = ks * 8;
        uint32_t a[2][4];
        #pragma unroll
        for (int t2 = 0; t2 < 2; t2++) {
            const uint32_t* ap = abase + t2 * 16 * LDP + k0;
            a[t2][0] = ap[0]; a[t2][1] = ap[8 * LDP];
            a[t2][2] = ap[4]; a[t2][3] = ap[8 * LDP + 4];
        }
        #pragma unroll
        for (int j = 0; j < 4; j++) {
            const uint32_t* bp = bbase + j * 8 * LDP + k0;
            uint32_t b[2]; b[0] = bp[0]; b[1] = bp[4];
            mma8(acc[0][j], a[0], b);
            mma8(acc[1][j], a[1], b);
        }
    }
    __half* outh = &g_qkv[slot][row0][0];
    #pragma unroll
    for (int t2 = 0; t2 < 2; t2++) {
        int r = mw * 32 + t2 * 16 + g;
        #pragma unroll
        for (int j = 0; j < 4; j++) {
            int c = nw * 32 + j * 8 + q * 2;
            *(uint32_t*)(outh + (size_t)r * DM + c)       = pack_h2(acc[t2][j][0], acc[t2][j][1]);
            *(uint32_t*)(outh + (size_t)(r + 8) * DM + c) = pack_h2(acc[t2][j][2], acc[t2][j][3]);
        }
    }
}

// ===========================================================================
// Kernel 3: sparse-masked attention. Block = (t,bp,h), 512 threads, one per
// query row. K/V read as fp16 from g_qkv, converted into the SAME fp32 SMEM
// layout as R4 (stride-32, lane-rotated float4 reads -> deterministic 4-phase
// crossbar). Direct exp; coalesced transposed CSR.
// ===========================================================================
__global__ void __launch_bounds__(512, 1)
attn_kernel() {
    extern __shared__ float smf[];
    float* Ks = smf;               // [512][32]
    float* Vs = smf + 512 * 32;    // [512][32]
    int tid = threadIdx.x;
    int h = blockIdx.x;
    int t = blockIdx.y >> 5, bp = blockIdx.y & 31;

    const __half* Kg = &g_qkv[t * 3 + 1][(size_t)bp * NN][0];
    const __half* Vg = &g_qkv[t * 3 + 2][(size_t)bp * NN][0];
    // stage: i covers (row m, 8-dim chunk c). fp16 load (16B = 8 halfs) -> fp32 smem
    for (int i = tid; i < 512 * 4; i += 512) {
        int m = i >> 2, c = i & 3;
        uint4 kk = *(const uint4*)(Kg + (size_t)m * DM + h * DK + c * 8);
        float2 f0 = __half22float2(*(__half2*)&kk.x);
        float2 f1 = __half22float2(*(__half2*)&kk.y);
        float2 f2 = __half22float2(*(__half2*)&kk.z);
        float2 f3 = __half22float2(*(__half2*)&kk.w);
        *(float4*)(Ks + m * 32 + c * 8)     = make_float4(f0.x, f0.y, f1.x, f1.y);
        *(float4*)(Ks + m * 32 + c * 8 + 4) = make_float4(f2.x, f2.y, f3.x, f3.y);
        uint4 vv = *(const uint4*)(Vg + (size_t)m * DM + h * DK + c * 8);
        f0 = __half22float2(*(__half2*)&vv.x);
        f1 = __half22float2(*(__half2*)&vv.y);
        f2 = __half22float2(*(__half2*)&vv.z);
        f3 = __half22float2(*(__half2*)&vv.w);
        *(float4*)(Vs + m * 32 + c * 8)     = make_float4(f0.x, f0.y, f1.x, f1.y);
        *(float4*)(Vs + m * 32 + c * 8 + 4) = make_float4(f2.x, f2.y, f3.x, f3.y);
    }
    __syncthreads();

    int n = tid;
    int gn = bp * NN + n;
    int rot = tid & 7;
    float4 qr[8];
    const __half* Qg = &g_qkv[t * 3 + 0][gn][h * DK];
    #pragma unroll
    for (int j = 0; j < 8; j++) {
        int jj = (j + rot) & 7;
        uint2 qv = *(const uint2*)(Qg + jj * 4);   // 4 halfs = one chunk
        float2 a = __half22float2(*(__half2*)&qv.x);
        float2 b = __half22float2(*(__half2*)&qv.y);
        qr[j] = make_float4(a.x, a.y, b.x, b.y);
    }
    int cnt = g_nnz[t][n];
    float Z = 0.f;
    float4 av[8];
    #pragma unroll
    for (int j = 0; j < 8; j++) av[j] = make_float4(0.f, 0.f, 0.f, 0.f);
    const float scale = 0.17677669529663687f;   // 1/sqrt(32)

    for (int i = 0; i < cnt; i++) {
        int m = g_colsT[t][i][n];        // coalesced: lanes = consecutive n
        float tv = g_valsT[t][i][n];
        const float* kb = Ks + m * 32;
        float s = 0.f;
        #pragma unroll
        for (int j = 0; j < 8; j++) {
            int jj = (j + rot) & 7;
            float4 k4 = *(const float4*)(kb + jj * 4);
            s += qr[j].x * k4.x + qr[j].y * k4.y + qr[j].z * k4.z + qr[j].w * k4.w;
        }
        float e = __expf(s * scale);
        Z += e;
        float we = tv * e;
        const float* vb = Vs + m * 32;
        #pragma unroll
        for (int j = 0; j < 8; j++) {
            int jj = (j + rot) & 7;
            float4 v4 = *(const float4*)(vb + jj * 4);
            av[j].x += we * v4.x;
            av[j].y += we * v4.y;
            av[j].z += we * v4.z;
            av[j].w += we * v4.w;
        }
    }
    float inv = 1.f / Z;
    float* out = &g_attn[t][gn][h * DK];
    #pragma unroll
    for (int j = 0; j < 8; j++) {
        int jj = (j + rot) & 7;
        float4 v = make_float4(av[j].x * inv, av[j].y * inv, av[j].z * inv, av[j].w * inv);
        *(float4*)(out + jj * 4) = v;
    }
}

// ===========================================================================
// Kernel 4: output projection via tf32 mma.sync (K=384 = 3 accumulated
// chunks), 512 threads / 16 warps, fused residual + warp-per-row LayerNorm.
// ===========================================================================
__global__ void __launch_bounds__(512, 1)
outproj_mma_kernel(const float* __restrict__ X,
                   const float* __restrict__ Wo,
                   const float* __restrict__ gamma,
                   const float* __restrict__ beta,
                   float* __restrict__ out) {
    extern __shared__ uint32_t sm[];
    uint32_t* As = sm;                 // [128][LDP]
    uint32_t* Ws = sm + 128 * LDP;     // [128][LDP]
    float* Ys = (float*)sm;            // reuse As after GEMM
    int tid = threadIdx.x, lane = tid & 31, wid = tid >> 5;
    int mw = wid & 3, nw = wid >> 2;
    int g = lane >> 2, q = lane & 3;
    int row0 = blockIdx.x * 128;

    const uint32_t* abase = As + (mw * 32 + g) * LDP + q;
    const uint32_t* bbase = Ws + (nw * 32 + g) * LDP + q;

    float acc[2][4][4];
    #pragma unroll
    for (int t2 = 0; t2 < 2; t2++)
        #pragma unroll
        for (int j = 0; j < 4; j++)
            #pragma unroll
            for (int e = 0; e < 4; e++) acc[t2][j][e] = 0.f;

    for (int t = 0; t < NT; t++) {
        __syncthreads();
        for (int i = tid; i < 128 * 32; i += 512) {
            int r = i >> 5, k = (i & 31) << 2;
            float4 a = *(const float4*)(&g_attn[t][row0 + r][k]);
            uint32_t* d = As + r * LDP + k;
            d[0] = f2tf32(a.x); d[1] = f2tf32(a.y); d[2] = f2tf32(a.z); d[3] = f2tf32(a.w);
            float4 w = *(const float4*)(Wo + (size_t)r * (NT * DM) + t * DM + k);
            uint32_t* d2 = Ws + r * LDP + k;
            d2[0] = f2tf32(w.x); d2[1] = f2tf32(w.y); d2[2] = f2tf32(w.z); d2[3] = f2tf32(w.w);
        }
        __syncthreads();
        #pragma unroll 4
        for (int ks = 0; ks < 16; ks++) {
            int k0 = ks * 8;
            uint32_t a[2][4];
            #pragma unroll
            for (int t2 = 0; t2 < 2; t2++) {
                const uint32_t* ap = abase + t2 * 16 * LDP + k0;
                a[t2][0] = ap[0]; a[t2][1] = ap[8 * LDP];
                a[t2][2] = ap[4]; a[t2][3] = ap[8 * LDP + 4];
            }
            #pragma unroll
            for (int j = 0; j < 4; j++) {
                const uint32_t* bp = bbase + j * 8 * LDP + k0;
                uint32_t b[2]; b[0] = bp[0]; b[1] = bp[4];
                mma8(acc[0][j], a[0], b);
                mma8(acc[1][j], a[1], b);
            }
        }
    }
    __syncthreads();
    #pragma unroll
    for (int t2 = 0; t2 < 2; t2++) {
        int r = mw * 32 + t2 * 16 + g;
        #pragma unroll
        for (int j = 0; j < 4; j++) {
            int c = nw * 32 + j * 8 + q * 2;
            *(float2*)(Ys + r * LDP + c)       = make_float2(acc[t2][j][0], acc[t2][j][1]);
            *(float2*)(Ys + (r + 8) * LDP + c) = make_float2(acc[t2][j][2], acc[t2][j][3]);
        }
    }
    __syncthreads();
    for (int r = wid; r < 128; r += 16) {
        float4 y  = *(float4*)(Ys + r * LDP + lane * 4);
        float4 xv = *(const float4*)(X + (size_t)(row0 + r) * DM + lane * 4);
        float v0 = y.x + xv.x, v1 = y.y + xv.y, v2 = y.z + xv.z, v3 = y.w + xv.w;
        float s  = v0 + v1 + v2 + v3;
        float s2 = v0 * v0 + v1 * v1 + v2 * v2 + v3 * v3;
        #pragma unroll
        for (int off = 16; off; off >>= 1) {
            s  += __shfl_xor_sync(0xffffffffu, s,  off);
            s2 += __shfl_xor_sync(0xffffffffu, s2, off);
        }
        float mu = s * (1.f / DM);
        float var = s2 * (1.f / DM) - mu * mu;
        float rs = rsqrtf(var + 1e-5f);
        float4 gv = *(const float4*)(gamma + lane * 4);
        float4 bv = *(const float4*)(beta + lane * 4);
        float4 res = make_float4((v0 - mu) * rs * gv.x + bv.x,
                                 (v1 - mu) * rs * gv.y + bv.y,
                                 (v2 - mu) * rs * gv.z + bv.z,
                                 (v3 - mu) * rs * gv.w + bv.w);
        *(float4*)(out + (size_t)(row0 + r) * DM + lane * 4) = res;
    }
}

// ===========================================================================
extern "C" void kernel_launch(void* const* d_in, const int* in_sizes, int n_in,
                              void* d_out, int out_size) {
    const float* inputs = (const float*)d_in[0];
    const float* tm     = (const float*)d_in[2];
    const float* Wq     = (const float*)d_in[3];
    const float* Wk     = (const float*)d_in[4];
    const float* Wv     = (const float*)d_in[5];
    const float* Wo     = (const float*)d_in[6];
    const float* gamma  = (const float*)d_in[7];
    const float* beta   = (const float*)d_in[8];
    float* out = (float*)d_out;

    int smem_qkv  = (64 + 128) * LDP * (int)sizeof(float);  // 101376
    int smem_attn = 2 * 512 * 32 * (int)sizeof(float);      // 131072
    int smem_out  = 2 * 128 * LDP * (int)sizeof(float);     // 135168
    cudaFuncSetAttribute(qkv_mma_kernel,     cudaFuncAttributeMaxDynamicSharedMemorySize, smem_qkv);
    cudaFuncSetAttribute(attn_kernel,        cudaFuncAttributeMaxDynamicSharedMemorySize, smem_attn);
    cudaFuncSetAttribute(outproj_mma_kernel, cudaFuncAttributeMaxDynamicSharedMemorySize, smem_out);

    build_csr_kernel<<<(NT * NN * 32 + 255) / 256, 256>>>(tm);
    qkv_mma_kernel<<<dim3(NROWS / 64, 9), 256, smem_qkv>>>(inputs, Wq, Wk, Wv);
    attn_kernel<<<dim3(NH, NT * NB * NP), 512, smem_attn>>>();
    outproj_mma_kernel<<<NROWS / 128, 512, smem_out>>>(inputs, Wo, gamma, beta, out);
}